// round 1
// baseline (speedup 1.0000x reference)
#include <cuda_runtime.h>
#include <cstdint>

#define HP   66
#define WPD  66
#define CIN  128
#define OC   128
#define HW   4096
#define NB   4
#define NS   9

// ---- device scratch (static allocation; no cudaMalloc allowed) ----
__device__ float  g_xpad[NB * HP * WPD * CIN];   // NHWC padded x, 8.9 MB
__device__ float  g_wk[NS * CIN * OC];           // weight transposed [n][c][oc]
__device__ float4 g_gw[NB * NS * HW];            // bilinear weights (lt, rb, lb, rt)
__device__ int4   g_gi[NB * NS * HW];            // flat indices into 66x66 plane

// ---------------- prep kernels ----------------

__global__ void pad_kernel(const float* __restrict__ x) {
    int c  = threadIdx.x;                 // 128
    int bi = blockIdx.x;                  // 4*66*66
    int wp = bi % WPD;
    int hp = (bi / WPD) % HP;
    int b  = bi / (HP * WPD);
    float v = 0.f;
    if (hp >= 1 && hp <= 64 && wp >= 1 && wp <= 64)
        v = x[((b * CIN + c) * 64 + (hp - 1)) * 64 + (wp - 1)];
    g_xpad[(b * HP * WPD + hp * WPD + wp) * CIN + c] = v;
}

__global__ void wk_kernel(const float* __restrict__ w) {
    int t  = blockIdx.x * 256 + threadIdx.x;   // 9*128*128 total
    int oc = t & 127;
    int c  = (t >> 7) & 127;
    int n  = t >> 14;
    g_wk[(n * CIN + c) * OC + oc] = w[(oc * CIN + c) * 9 + n];
}

__global__ void coef_kernel(const float* __restrict__ off) {
    int t   = blockIdx.x * 256 + threadIdx.x;  // 4*9*4096 total
    int pix = t & 4095;
    int n   = (t >> 12) % 9;
    int b   = t / (9 * 4096);
    int i   = pix >> 6, j = pix & 63;

    float ox = off[(b * 18 + 2 * n)     * HW + pix];
    float oy = off[(b * 18 + 2 * n + 1) * HW + pix];
    // p0 + p_n + offset : p0 = (i+1, j+1), p_n = (n/3 - 1, n%3 - 1)
    float px = (float)(i + n / 3) + ox;
    float py = (float)(j + n % 3) + oy;
    float fx = floorf(px), fy = floorf(py);
    int qltx = min(max((int)fx, 0), 65);
    int qlty = min(max((int)fy, 0), 65);
    int qrbx = min(max((int)fx + 1, 0), 65);
    int qrby = min(max((int)fy + 1, 0), 65);
    // boundary mask (reference: px<PAD || px>Hp-1-PAD -> snap to floor), then clip
    if (px < 1.f || px > 64.f) px = fx;
    if (py < 1.f || py > 64.f) py = fy;
    px = fminf(fmaxf(px, 0.f), 65.f);
    py = fminf(fmaxf(py, 0.f), 65.f);

    float dltx = 1.f + (float)qltx - px;
    float dlty = 1.f + (float)qlty - py;
    float drbx = 1.f - ((float)qrbx - px);
    float drby = 1.f - ((float)qrby - py);

    g_gw[t] = make_float4(dltx * dlty, drbx * drby, dltx * drby, drbx * dlty);
    g_gi[t] = make_int4(qltx * WPD + qlty, qrbx * WPD + qrby,
                        qltx * WPD + qrby, qrbx * WPD + qlty);
}

// ---------------- main fused gather + GEMM kernel ----------------

__device__ __forceinline__ unsigned long long dup2(float x) {
    unsigned long long r;
    unsigned int xi = __float_as_uint(x);
    asm("mov.b64 %0, {%1, %1};" : "=l"(r) : "r"(xi));
    return r;
}

#define FFMA2(d, a, bb) \
    asm("fma.rn.f32x2 %0, %1, %2, %0;" : "+l"(d) : "l"(a), "l"(bb))

__global__ __launch_bounds__(256, 1) void main_kernel(float* __restrict__ out) {
    __shared__ float As[32][132];   // [c-chunk k][oc], padded
    __shared__ float Bs[32][132];   // [c-chunk k][pixel], padded

    int t       = threadIdx.x;
    int b       = blockIdx.x >> 5;
    int pixbase = (blockIdx.x & 31) << 7;    // 128 pixels per block
    int tx = t & 15, ty = t >> 4;            // micro-tile: 8 oc (ty) x 8 pix (tx)

    unsigned long long acc[8][4];            // 8 oc x 4 f32x2 pixel pairs
    #pragma unroll
    for (int ii = 0; ii < 8; ii++)
        #pragma unroll
        for (int jj = 0; jj < 4; jj++) acc[ii][jj] = 0ULL;

    const float* xb = g_xpad + b * (HP * WPD * CIN);
    int c4   = t & 7;     // which float4 of the 32-c chunk this thread gathers
    int prow = t >> 3;    // 0..31 : pixel row within pass

    for (int n = 0; n < NS; n++) {
        const float4* __restrict__ gwp = g_gw + (b * NS + n) * HW + pixbase;
        const int4*  __restrict__  gip = g_gi + (b * NS + n) * HW + pixbase;
        #pragma unroll 1
        for (int cc = 0; cc < 4; cc++) {
            // ---- load A tile: wk[n][cc*32 + k][oc] ----
            const float* wkbase = g_wk + (n * CIN + cc * 32) * OC;
            #pragma unroll
            for (int it = 0; it < 4; it++) {
                int idx = it * 256 + t;
                int k = idx >> 5, o4 = idx & 31;
                *(float4*)&As[k][o4 * 4] =
                    *(const float4*)(wkbase + k * OC + o4 * 4);
            }
            // ---- build B tile: bilinear-gathered x_off for 32 c x 128 pix ----
            const float* cb = xb + cc * 32 + c4 * 4;
            #pragma unroll
            for (int pass = 0; pass < 4; pass++) {
                int p = pass * 32 + prow;
                float4 gw = gwp[p];
                int4   gi = gip[p];
                float4 v0 = *(const float4*)(cb + (long)gi.x * CIN);
                float4 v1 = *(const float4*)(cb + (long)gi.y * CIN);
                float4 v2 = *(const float4*)(cb + (long)gi.z * CIN);
                float4 v3 = *(const float4*)(cb + (long)gi.w * CIN);
                Bs[c4 * 4 + 0][p] = gw.x*v0.x + gw.y*v1.x + gw.z*v2.x + gw.w*v3.x;
                Bs[c4 * 4 + 1][p] = gw.x*v0.y + gw.y*v1.y + gw.z*v2.y + gw.w*v3.y;
                Bs[c4 * 4 + 2][p] = gw.x*v0.z + gw.y*v1.z + gw.z*v2.z + gw.w*v3.z;
                Bs[c4 * 4 + 3][p] = gw.x*v0.w + gw.y*v1.w + gw.z*v2.w + gw.w*v3.w;
            }
            __syncthreads();
            // ---- GEMM micro-kernel with packed f32x2 FMAs ----
            #pragma unroll
            for (int k = 0; k < 32; k++) {
                float4 a0 = *(const float4*)&As[k][ty * 8];
                float4 a1 = *(const float4*)&As[k][ty * 8 + 4];
                ulonglong2 bp0 = *(const ulonglong2*)&Bs[k][tx * 8];
                ulonglong2 bp1 = *(const ulonglong2*)&Bs[k][tx * 8 + 4];
                unsigned long long bv0 = bp0.x, bv1 = bp0.y,
                                   bv2 = bp1.x, bv3 = bp1.y;
                float av[8] = {a0.x, a0.y, a0.z, a0.w, a1.x, a1.y, a1.z, a1.w};
                #pragma unroll
                for (int ii = 0; ii < 8; ii++) {
                    unsigned long long ad = dup2(av[ii]);
                    FFMA2(acc[ii][0], ad, bv0);
                    FFMA2(acc[ii][1], ad, bv1);
                    FFMA2(acc[ii][2], ad, bv2);
                    FFMA2(acc[ii][3], ad, bv3);
                }
            }
            __syncthreads();
        }
    }

    // ---- epilogue: out is NCHW [b][oc][pix] ----
    float* ob = out + (size_t)(b * OC) * HW + pixbase;
    #pragma unroll
    for (int ii = 0; ii < 8; ii++) {
        int oc = ty * 8 + ii;
        float2 f0 = *(float2*)&acc[ii][0];
        float2 f1 = *(float2*)&acc[ii][1];
        float2 f2 = *(float2*)&acc[ii][2];
        float2 f3 = *(float2*)&acc[ii][3];
        float4 s0 = make_float4(f0.x, f0.y, f1.x, f1.y);
        float4 s1 = make_float4(f2.x, f2.y, f3.x, f3.y);
        *(float4*)(ob + (size_t)oc * HW + tx * 8)     = s0;
        *(float4*)(ob + (size_t)oc * HW + tx * 8 + 4) = s1;
    }
}

// ---------------- launch ----------------

extern "C" void kernel_launch(void* const* d_in, const int* in_sizes, int n_in,
                              void* d_out, int out_size) {
    const float* x   = (const float*)d_in[0];
    const float* off = (const float*)d_in[1];
    const float* w   = (const float*)d_in[2];
    float* out = (float*)d_out;
    (void)in_sizes; (void)n_in; (void)out_size;

    pad_kernel <<<NB * HP * WPD, CIN>>>(x);
    wk_kernel  <<<(NS * CIN * OC) / 256, 256>>>(w);
    coef_kernel<<<(NB * NS * HW) / 256, 256>>>(off);
    main_kernel<<<128, 256>>>(out);
}

// round 3
// speedup vs baseline: 2.4920x; 2.4920x over previous
#include <cuda_runtime.h>
#include <cstdint>

#define HPAD   66
#define CIN    128
#define OC     128
#define HW     4096
#define NB     4
#define NS     9
#define NCHUNK 36

// ---- device scratch ----
__device__ float  g_xpad[NB * HPAD * HPAD * CIN];   // NHWC padded x
__device__ float  g_wk2[NS * OC * CIN];             // [n][oc][c], tf32-rounded
__device__ float4 g_gw[NB * NS * HW];               // bilinear weights
__device__ int4   g_gi[NB * NS * HW];               // gather indices (66x66 plane)

// ---- dynamic smem layout (bytes) ----
#define SM_TPTR  0
#define SM_MBAR0 16
#define SM_MBAR1 24
#define SM_A0    1024
#define SM_A1    17408
#define SM_B0    33792
#define SM_B1    50176
#define SM_TS    66560
#define SM_TOTAL 83456

#define TMEM_COLS 128
// idesc kind::tf32: dtype=F32(1)<<4, atype=TF32(2)<<7, btype=TF32(2)<<10,
// N>>3 (16)<<17, M>>4 (8)<<24
#define IDESC 0x8200910u

#define SW128(o) ((o) ^ (((o) >> 3) & 0x70))

// Feature gate: tcgen05 only exists in the compute_103a device pass.
#if !defined(__CUDA_ARCH__) || defined(__CUDA_ARCH_FEAT_SM103_ALL)
#define HAS_TCGEN05 1
#else
#define HAS_TCGEN05 0
#endif

// ---------------- PTX helpers ----------------
__device__ __forceinline__ uint32_t smem_u32(const void* p) {
    uint32_t a;
    asm("{ .reg .u64 t; cvta.to.shared.u64 t, %1; cvt.u32.u64 %0, t; }" : "=r"(a) : "l"(p));
    return a;
}
__device__ __forceinline__ float ftf32(float x) {
    uint32_t r; asm("cvt.rna.tf32.f32 %0, %1;" : "=r"(r) : "f"(x));
    return __uint_as_float(r);
}
__device__ __forceinline__ uint64_t mkdesc(uint32_t addr) {
    const uint64_t base = (2ull << 61) | (1ull << 46) | (64ull << 32) | (1ull << 16);
    return base | ((uint64_t)(addr >> 4) & 0x3FFF);
}
__device__ __forceinline__ void mbar_init(uint32_t a, uint32_t cnt) {
    asm volatile("mbarrier.init.shared.b64 [%0], %1;" :: "r"(a), "r"(cnt) : "memory");
}
__device__ __forceinline__ void mbar_wait(uint32_t a, uint32_t par) {
    uint32_t done;
    asm volatile(
        "{\n\t.reg .pred p;\n\t"
        "mbarrier.try_wait.parity.acquire.cta.shared::cta.b64 p, [%1], %2;\n\t"
        "selp.b32 %0, 1, 0, p;\n\t}"
        : "=r"(done) : "r"(a), "r"(par) : "memory");
    if (!done) {
        asm volatile(
            "{\n\t.reg .pred P1;\n\t"
            "W%=:\n\t"
            "mbarrier.try_wait.parity.acquire.cta.shared::cta.b64 P1, [%0], %1, 0x989680;\n\t"
            "@P1 bra.uni D%=;\n\t"
            "bra.uni W%=;\n\t"
            "D%=:\n\t}"
            :: "r"(a), "r"(par) : "memory");
    }
}

#if HAS_TCGEN05
__device__ __forceinline__ void mma_tf32(uint32_t d, uint64_t ad, uint64_t bd, bool acc) {
    uint32_t e = acc ? 1u : 0u, z = 0u;
    asm volatile(
        "{\n\t.reg .pred p;\n\tsetp.ne.u32 p, %5, 0;\n\t"
        "tcgen05.mma.cta_group::1.kind::tf32 [%0], %1, %2, %3, {%4,%4,%4,%4}, p;\n\t}"
        :: "r"(d), "l"(ad), "l"(bd), "r"(IDESC), "r"(z), "r"(e) : "memory");
}
__device__ __forceinline__ void mma_commit(uint32_t mbar) {
    asm volatile(
        "tcgen05.commit.cta_group::1.mbarrier::arrive::one.shared::cluster.b64 [%0];"
        :: "r"(mbar) : "memory");
}
__device__ __forceinline__ void ldtm32(uint32_t* r, uint32_t ta) {
    asm volatile(
        "tcgen05.ld.sync.aligned.32x32b.x32.b32 "
        "{%0,%1,%2,%3,%4,%5,%6,%7,%8,%9,%10,%11,%12,%13,%14,%15,"
        "%16,%17,%18,%19,%20,%21,%22,%23,%24,%25,%26,%27,%28,%29,%30,%31}, [%32];"
        : "=r"(r[0]),"=r"(r[1]),"=r"(r[2]),"=r"(r[3]),"=r"(r[4]),"=r"(r[5]),"=r"(r[6]),"=r"(r[7]),
          "=r"(r[8]),"=r"(r[9]),"=r"(r[10]),"=r"(r[11]),"=r"(r[12]),"=r"(r[13]),"=r"(r[14]),"=r"(r[15]),
          "=r"(r[16]),"=r"(r[17]),"=r"(r[18]),"=r"(r[19]),"=r"(r[20]),"=r"(r[21]),"=r"(r[22]),"=r"(r[23]),
          "=r"(r[24]),"=r"(r[25]),"=r"(r[26]),"=r"(r[27]),"=r"(r[28]),"=r"(r[29]),"=r"(r[30]),"=r"(r[31])
        : "r"(ta));
}
#endif

// ---------------- prep kernels ----------------
__global__ void pad_kernel(const float* __restrict__ x) {
    int c  = threadIdx.x;
    int bi = blockIdx.x;
    int wp = bi % HPAD;
    int hp = (bi / HPAD) % HPAD;
    int b  = bi / (HPAD * HPAD);
    float v = 0.f;
    if (hp >= 1 && hp <= 64 && wp >= 1 && wp <= 64)
        v = x[((b * CIN + c) * 64 + (hp - 1)) * 64 + (wp - 1)];
    g_xpad[(b * HPAD * HPAD + hp * HPAD + wp) * CIN + c] = v;
}

__global__ void wk_kernel(const float* __restrict__ w) {
    int t  = blockIdx.x * 256 + threadIdx.x;     // 9*128*128
    int c  = t & 127;
    int oc = (t >> 7) & 127;
    int n  = t >> 14;
    g_wk2[(n * OC + oc) * CIN + c] = ftf32(w[(oc * CIN + c) * 9 + n]);
}

__global__ void coef_kernel(const float* __restrict__ off) {
    int t   = blockIdx.x * 256 + threadIdx.x;    // 4*9*4096
    int pix = t & 4095;
    int n   = (t >> 12) % 9;
    int b   = t / (9 * 4096);
    int i   = pix >> 6, j = pix & 63;

    float ox = off[(b * 18 + 2 * n)     * HW + pix];
    float oy = off[(b * 18 + 2 * n + 1) * HW + pix];
    float px = (float)(i + n / 3) + ox;
    float py = (float)(j + n % 3) + oy;
    float fx = floorf(px), fy = floorf(py);
    int qltx = min(max((int)fx, 0), 65);
    int qlty = min(max((int)fy, 0), 65);
    int qrbx = min(max((int)fx + 1, 0), 65);
    int qrby = min(max((int)fy + 1, 0), 65);
    if (px < 1.f || px > 64.f) px = fx;
    if (py < 1.f || py > 64.f) py = fy;
    px = fminf(fmaxf(px, 0.f), 65.f);
    py = fminf(fmaxf(py, 0.f), 65.f);

    float dltx = 1.f + (float)qltx - px;
    float dlty = 1.f + (float)qlty - py;
    float drbx = 1.f - ((float)qrbx - px);
    float drby = 1.f - ((float)qrby - py);

    g_gw[t] = make_float4(dltx * dlty, drbx * drby, dltx * drby, drbx * dlty);
    g_gi[t] = make_int4(qltx * HPAD + qlty, qrbx * HPAD + qrby,
                        qltx * HPAD + qrby, qrbx * HPAD + qlty);
}

// ---------------- main fused gather + tcgen05 TF32 GEMM ----------------
__global__ __launch_bounds__(256, 1) void main_kernel(float* __restrict__ out) {
#if HAS_TCGEN05
    extern __shared__ char sm[];
    uint32_t smb = smem_u32(sm);
    int tid  = threadIdx.x;
    int wid  = tid >> 5;
    int lane = tid & 31;
    int b       = blockIdx.x >> 5;
    int pixbase = (blockIdx.x & 31) << 7;

    const uint32_t A_OFF[2] = {SM_A0, SM_A1};
    const uint32_t B_OFF[2] = {SM_B0, SM_B1};
    const uint32_t MB[2]    = {smb + SM_MBAR0, smb + SM_MBAR1};

    if (wid == 0)
        asm volatile("tcgen05.alloc.cta_group::1.sync.aligned.shared::cta.b32 [%0], %1;"
                     :: "r"(smb + SM_TPTR), "r"((uint32_t)TMEM_COLS) : "memory");
    if (tid == 0) { mbar_init(MB[0], 1); mbar_init(MB[1], 1); }

    const float*  xb  = g_xpad + (size_t)b * HPAD * HPAD * CIN;
    int c4 = tid & 7, r0 = tid >> 3;

#define BUILD_CHUNK(N_, CC_, BUF_) do {                                         \
        const float* wkb = g_wk2 + ((size_t)(N_) * OC) * CIN + (CC_) * 32 + c4 * 4; \
        char* As = sm + A_OFF[BUF_];                                            \
        char* Bs = sm + B_OFF[BUF_];                                            \
        const float4* gwp = g_gw + ((size_t)b * NS + (N_)) * HW + pixbase;      \
        const int4*   gip = g_gi + ((size_t)b * NS + (N_)) * HW + pixbase;      \
        const float*  cb  = xb + (CC_) * 32 + c4 * 4;                           \
        _Pragma("unroll")                                                       \
        for (int pass = 0; pass < 4; pass++) {                                  \
            int oc = r0 + 32 * pass;                                            \
            float4 v = *(const float4*)(wkb + (size_t)oc * CIN);                \
            uint32_t o = oc * 128 + c4 * 16;                                    \
            *(float4*)(As + SW128(o)) = v;                                      \
        }                                                                       \
        _Pragma("unroll")                                                       \
        for (int pass = 0; pass < 4; pass++) {                                  \
            int p = r0 + 32 * pass;                                             \
            float4 gw = gwp[p];                                                 \
            int4   gi = gip[p];                                                 \
            float4 v0 = *(const float4*)(cb + (size_t)gi.x * CIN);              \
            float4 v1 = *(const float4*)(cb + (size_t)gi.y * CIN);              \
            float4 v2 = *(const float4*)(cb + (size_t)gi.z * CIN);              \
            float4 v3 = *(const float4*)(cb + (size_t)gi.w * CIN);              \
            float4 r;                                                           \
            r.x = ftf32(gw.x*v0.x + gw.y*v1.x + gw.z*v2.x + gw.w*v3.x);         \
            r.y = ftf32(gw.x*v0.y + gw.y*v1.y + gw.z*v2.y + gw.w*v3.y);         \
            r.z = ftf32(gw.x*v0.z + gw.y*v1.z + gw.z*v2.z + gw.w*v3.z);         \
            r.w = ftf32(gw.x*v0.w + gw.y*v1.w + gw.z*v2.w + gw.w*v3.w);         \
            uint32_t o = p * 128 + c4 * 16;                                     \
            *(float4*)(Bs + SW128(o)) = r;                                      \
        }                                                                       \
    } while (0)

    BUILD_CHUNK(0, 0, 0);
    asm volatile("fence.proxy.async.shared::cta;" ::: "memory");
    __syncthreads();

    uint32_t tmem_base;
    asm volatile("ld.shared.b32 %0, [%1];" : "=r"(tmem_base) : "r"(smb + SM_TPTR));
    uint32_t tmem_d = tmem_base;

    int par[2] = {0, 0};
    for (int i = 0; i < NCHUNK; i++) {
        int buf = i & 1;
        if (tid == 0) {
            uint64_t ad = mkdesc(smb + A_OFF[buf]);
            uint64_t bd = mkdesc(smb + B_OFF[buf]);
            #pragma unroll
            for (int k = 0; k < 4; k++)
                mma_tf32(tmem_d, ad + 2 * k, bd + 2 * k, (i > 0) || (k > 0));
            mma_commit(MB[buf]);
        }
        if (i + 1 < NCHUNK) {
            int nb = 1 - buf;
            if (i >= 1) { mbar_wait(MB[nb], par[nb]); par[nb] ^= 1; }
            int j = i + 1;
            BUILD_CHUNK(j >> 2, j & 3, nb);
            asm volatile("fence.proxy.async.shared::cta;" ::: "memory");
        }
        __syncthreads();
    }
    mbar_wait(MB[1], par[1]);
    asm volatile("tcgen05.fence::after_thread_sync;" ::: "memory");

    // epilogue: TMEM -> smem transpose -> coalesced STG
    float* Ts = (float*)(sm + SM_TS);
    for (int cg = 0; cg < 4; cg++) {
        if (wid < 4) {
            uint32_t r[32];
            ldtm32(r, tmem_d + cg * 32);
            asm volatile("tcgen05.wait::ld.sync.aligned;" ::: "memory");
            int oc = wid * 32 + lane;
            #pragma unroll
            for (int c = 0; c < 32; c++) Ts[oc * 33 + c] = __uint_as_float(r[c]);
        }
        __syncthreads();
        {
            int ocr = tid >> 1, half = (tid & 1) * 16;
            const float* row = Ts + ocr * 33 + half;
            float* op = out + ((size_t)(b * OC + ocr)) * HW + pixbase + cg * 32 + half;
            #pragma unroll
            for (int g = 0; g < 4; g++) {
                float4 v = make_float4(row[4*g], row[4*g+1], row[4*g+2], row[4*g+3]);
                *(float4*)(op + 4 * g) = v;
            }
        }
        __syncthreads();
    }

    if (wid == 0) {
        asm volatile("tcgen05.relinquish_alloc_permit.cta_group::1.sync.aligned;");
        asm volatile("tcgen05.dealloc.cta_group::1.sync.aligned.b32 %0, %1;"
                     :: "r"(tmem_base), "r"((uint32_t)TMEM_COLS));
    }
#undef BUILD_CHUNK
#else
    (void)out;   // non-103a PTX pass: dead body; sm_103a cubin is selected at runtime
#endif
}

// ---------------- launch ----------------
extern "C" void kernel_launch(void* const* d_in, const int* in_sizes, int n_in,
                              void* d_out, int out_size) {
    const float* x   = (const float*)d_in[0];
    const float* off = (const float*)d_in[1];
    const float* w   = (const float*)d_in[2];
    float* out = (float*)d_out;
    (void)in_sizes; (void)n_in; (void)out_size;

    cudaFuncSetAttribute(main_kernel, cudaFuncAttributeMaxDynamicSharedMemorySize, SM_TOTAL);

    pad_kernel <<<NB * HPAD * HPAD, CIN>>>(x);
    wk_kernel  <<<(NS * OC * CIN) / 256, 256>>>(w);
    coef_kernel<<<(NB * NS * HW) / 256, 256>>>(off);
    main_kernel<<<128, 256, SM_TOTAL>>>(out);
}

// round 4
// speedup vs baseline: 2.9447x; 1.1816x over previous
#include <cuda_runtime.h>
#include <cstdint>

#define HPAD   66
#define CIN    128
#define OC     128
#define HW     4096
#define NB     4
#define NS     9
#define NCHUNK 36
#define STAGES 3

// ---- device scratch ----
__device__ float  g_xpad[NB * HPAD * HPAD * CIN];   // NHWC padded x
__device__ float  g_wk2[NS * OC * CIN];             // [n][oc][c], tf32-rounded
__device__ float4 g_gw[NB * NS * HW];               // bilinear weights
__device__ int4   g_gi[NB * NS * HW];               // gather indices (66x66 plane)

// ---- dynamic smem layout (bytes) ----
#define SM_TPTR   0
#define SM_FULL(s)  (16 + 8 * (s))
#define SM_EMPTY(s) (48 + 8 * (s))
#define SM_A(s)   (1024 + (s) * 32768)
#define SM_B(s)   (SM_A(s) + 16384)
#define SM_TS     99328
#define SM_TOTAL  (99328 + 128 * 33 * 4)

#define TMEM_COLS 128
// idesc kind::tf32: dtype=F32(1)<<4, atype=TF32(2)<<7, btype=TF32(2)<<10,
// N>>3 (16)<<17, M>>4 (8)<<24
#define IDESC 0x8200910u

#define SW128(o) ((o) ^ (((o) >> 3) & 0x70))

// Feature gate: tcgen05 only exists in the compute_103a device pass.
#if !defined(__CUDA_ARCH__) || defined(__CUDA_ARCH_FEAT_SM103_ALL)
#define HAS_TCGEN05 1
#else
#define HAS_TCGEN05 0
#endif

// ---------------- PTX helpers ----------------
__device__ __forceinline__ uint32_t smem_u32(const void* p) {
    uint32_t a;
    asm("{ .reg .u64 t; cvta.to.shared.u64 t, %1; cvt.u32.u64 %0, t; }" : "=r"(a) : "l"(p));
    return a;
}
__device__ __forceinline__ float ftf32(float x) {
    uint32_t r; asm("cvt.rna.tf32.f32 %0, %1;" : "=r"(r) : "f"(x));
    return __uint_as_float(r);
}
__device__ __forceinline__ uint64_t mkdesc(uint32_t addr) {
    const uint64_t base = (2ull << 61) | (1ull << 46) | (64ull << 32) | (1ull << 16);
    return base | ((uint64_t)(addr >> 4) & 0x3FFF);
}
__device__ __forceinline__ void mbar_init(uint32_t a, uint32_t cnt) {
    asm volatile("mbarrier.init.shared.b64 [%0], %1;" :: "r"(a), "r"(cnt) : "memory");
}
__device__ __forceinline__ void mbar_arrive(uint32_t a) {
    asm volatile("mbarrier.arrive.shared.b64 _, [%0];" :: "r"(a) : "memory");
}
__device__ __forceinline__ void mbar_wait(uint32_t a, uint32_t par) {
    uint32_t done;
    asm volatile(
        "{\n\t.reg .pred p;\n\t"
        "mbarrier.try_wait.parity.acquire.cta.shared::cta.b64 p, [%1], %2;\n\t"
        "selp.b32 %0, 1, 0, p;\n\t}"
        : "=r"(done) : "r"(a), "r"(par) : "memory");
    if (!done) {
        asm volatile(
            "{\n\t.reg .pred P1;\n\t"
            "W%=:\n\t"
            "mbarrier.try_wait.parity.acquire.cta.shared::cta.b64 P1, [%0], %1, 0x989680;\n\t"
            "@P1 bra.uni D%=;\n\t"
            "bra.uni W%=;\n\t"
            "D%=:\n\t}"
            :: "r"(a), "r"(par) : "memory");
    }
}

#if HAS_TCGEN05
__device__ __forceinline__ void mma_tf32(uint32_t d, uint64_t ad, uint64_t bd, bool acc) {
    uint32_t e = acc ? 1u : 0u, z = 0u;
    asm volatile(
        "{\n\t.reg .pred p;\n\tsetp.ne.u32 p, %5, 0;\n\t"
        "tcgen05.mma.cta_group::1.kind::tf32 [%0], %1, %2, %3, {%4,%4,%4,%4}, p;\n\t}"
        :: "r"(d), "l"(ad), "l"(bd), "r"(IDESC), "r"(z), "r"(e) : "memory");
}
__device__ __forceinline__ void mma_commit(uint32_t mbar) {
    asm volatile(
        "tcgen05.commit.cta_group::1.mbarrier::arrive::one.shared::cluster.b64 [%0];"
        :: "r"(mbar) : "memory");
}
__device__ __forceinline__ void ldtm32(uint32_t* r, uint32_t ta) {
    asm volatile(
        "tcgen05.ld.sync.aligned.32x32b.x32.b32 "
        "{%0,%1,%2,%3,%4,%5,%6,%7,%8,%9,%10,%11,%12,%13,%14,%15,"
        "%16,%17,%18,%19,%20,%21,%22,%23,%24,%25,%26,%27,%28,%29,%30,%31}, [%32];"
        : "=r"(r[0]),"=r"(r[1]),"=r"(r[2]),"=r"(r[3]),"=r"(r[4]),"=r"(r[5]),"=r"(r[6]),"=r"(r[7]),
          "=r"(r[8]),"=r"(r[9]),"=r"(r[10]),"=r"(r[11]),"=r"(r[12]),"=r"(r[13]),"=r"(r[14]),"=r"(r[15]),
          "=r"(r[16]),"=r"(r[17]),"=r"(r[18]),"=r"(r[19]),"=r"(r[20]),"=r"(r[21]),"=r"(r[22]),"=r"(r[23]),
          "=r"(r[24]),"=r"(r[25]),"=r"(r[26]),"=r"(r[27]),"=r"(r[28]),"=r"(r[29]),"=r"(r[30]),"=r"(r[31])
        : "r"(ta));
}
#endif

// ---------------- prep kernels ----------------
// pad + NCHW->NHWC transpose, smem-staged for coalescing on both sides.
__global__ __launch_bounds__(256) void pad_kernel(const float* __restrict__ x) {
    __shared__ float ts[128 * 65];
    int bk  = blockIdx.x;
    int hp  = bk % HPAD;
    int b   = bk / HPAD;
    int tid = threadIdx.x;
    bool irow = (hp >= 1 && hp <= 64);
    if (irow) {
        const float* xr = x + ((size_t)b * CIN) * 4096 + (size_t)(hp - 1) * 64;
        #pragma unroll
        for (int i = 0; i < 32; i++) {
            int idx = tid + i * 256;
            int c = idx >> 6, wp = idx & 63;
            ts[c * 65 + wp] = xr[(size_t)c * 4096 + wp];
        }
    }
    __syncthreads();
    float* orow = g_xpad + ((size_t)(b * HPAD + hp)) * HPAD * CIN;
    #pragma unroll
    for (int i = 0; i < 9; i++) {
        int idx = tid + i * 256;              // over 66*128/4 = 2112 float4
        if (idx >= 2112) break;
        int wp = idx >> 5, c4i = idx & 31;
        float4 v = make_float4(0.f, 0.f, 0.f, 0.f);
        if (irow && wp >= 1 && wp <= 64) {
            int c = c4i * 4, w = wp - 1;
            v = make_float4(ts[c * 65 + w], ts[(c + 1) * 65 + w],
                            ts[(c + 2) * 65 + w], ts[(c + 3) * 65 + w]);
        }
        *(float4*)(orow + (size_t)idx * 4) = v;
    }
}

// fused: weight transpose+tf32 round AND bilinear coef precompute (both 147456 items)
__global__ void wkcoef_kernel(const float* __restrict__ w, const float* __restrict__ off) {
    int t = blockIdx.x * 256 + threadIdx.x;
    {   // weight: [n][oc][c] <- w[oc][c][n]
        int c  = t & 127;
        int oc = (t >> 7) & 127;
        int n  = t >> 14;
        g_wk2[(n * OC + oc) * CIN + c] = ftf32(w[(oc * CIN + c) * 9 + n]);
    }
    {   // coefs
        int pix = t & 4095;
        int n   = (t >> 12) % 9;
        int b   = t / (9 * 4096);
        int i   = pix >> 6, j = pix & 63;
        float ox = off[(b * 18 + 2 * n)     * HW + pix];
        float oy = off[(b * 18 + 2 * n + 1) * HW + pix];
        float px = (float)(i + n / 3) + ox;
        float py = (float)(j + n % 3) + oy;
        float fx = floorf(px), fy = floorf(py);
        int qltx = min(max((int)fx, 0), 65);
        int qlty = min(max((int)fy, 0), 65);
        int qrbx = min(max((int)fx + 1, 0), 65);
        int qrby = min(max((int)fy + 1, 0), 65);
        if (px < 1.f || px > 64.f) px = fx;
        if (py < 1.f || py > 64.f) py = fy;
        px = fminf(fmaxf(px, 0.f), 65.f);
        py = fminf(fmaxf(py, 0.f), 65.f);
        float dltx = 1.f + (float)qltx - px;
        float dlty = 1.f + (float)qlty - py;
        float drbx = 1.f - ((float)qrbx - px);
        float drby = 1.f - ((float)qrby - py);
        g_gw[t] = make_float4(dltx * dlty, drbx * drby, dltx * drby, drbx * dlty);
        g_gi[t] = make_int4(qltx * HPAD + qlty, qrbx * HPAD + qrby,
                            qltx * HPAD + qrby, qrbx * HPAD + qlty);
    }
}

// ---------------- main fused gather + tcgen05 TF32 GEMM (3-stage ring) ----------------
__global__ __launch_bounds__(512, 1) void main_kernel(float* __restrict__ out) {
#if HAS_TCGEN05
    extern __shared__ char sm[];
    uint32_t smb = smem_u32(sm);
    int tid  = threadIdx.x;
    int wid  = tid >> 5;
    int lane = tid & 31;
    int b       = blockIdx.x >> 5;
    int pixbase = (blockIdx.x & 31) << 7;

    if (wid == 0)
        asm volatile("tcgen05.alloc.cta_group::1.sync.aligned.shared::cta.b32 [%0], %1;"
                     :: "r"(smb + SM_TPTR), "r"((uint32_t)TMEM_COLS) : "memory");
    if (tid == 0) {
        #pragma unroll
        for (int s = 0; s < STAGES; s++) {
            mbar_init(smb + SM_FULL(s), 512);
            mbar_init(smb + SM_EMPTY(s), 1);
        }
    }
    __syncthreads();

    uint32_t tmem_base;
    asm volatile("ld.shared.b32 %0, [%1];" : "=r"(tmem_base) : "r"(smb + SM_TPTR));

    const float* xb = g_xpad + (size_t)b * HPAD * HPAD * CIN;
    int c4 = tid & 7, r0 = tid >> 3;                 // c4: 16B group, r0: 0..63

    float4 cw0, cw1; int4 ci0, ci1;                  // coef cache (2 pixels)
    int s = 0;                                       // ring stage
    int rnd = 0;                                     // ring round = j/STAGES

    for (int j = 0; j < NCHUNK; j++) {
        int n = j >> 2, cc = j & 3;
        if (cc == 0) {
            const float4* gwp = g_gw + ((size_t)b * NS + n) * HW + pixbase;
            const int4*   gip = g_gi + ((size_t)b * NS + n) * HW + pixbase;
            cw0 = gwp[r0];      ci0 = gip[r0];
            cw1 = gwp[r0 + 64]; ci1 = gip[r0 + 64];
        }
        if (j >= STAGES) mbar_wait(smb + SM_EMPTY(s), (rnd - 1) & 1);

        char* As = sm + SM_A(s);
        char* Bs = sm + SM_B(s);
        // ---- A tile: wk2[n][oc][cc*32 + c4*4 ..+4], rows oc = r0, r0+64 ----
        {
            const float* wkb = g_wk2 + ((size_t)n * OC) * CIN + cc * 32 + c4 * 4;
            float4 a0 = *(const float4*)(wkb + (size_t)r0 * CIN);
            float4 a1 = *(const float4*)(wkb + (size_t)(r0 + 64) * CIN);
            *(float4*)(As + SW128(r0 * 128 + c4 * 16)) = a0;
            *(float4*)(As + SW128((r0 + 64) * 128 + c4 * 16)) = a1;
        }
        // ---- B tile: bilinear gather for pixels r0 and r0+64 ----
        {
            const float* cb = xb + cc * 32 + c4 * 4;
            float4 v0 = *(const float4*)(cb + (size_t)ci0.x * CIN);
            float4 v1 = *(const float4*)(cb + (size_t)ci0.y * CIN);
            float4 v2 = *(const float4*)(cb + (size_t)ci0.z * CIN);
            float4 v3 = *(const float4*)(cb + (size_t)ci0.w * CIN);
            float4 u0 = *(const float4*)(cb + (size_t)ci1.x * CIN);
            float4 u1 = *(const float4*)(cb + (size_t)ci1.y * CIN);
            float4 u2 = *(const float4*)(cb + (size_t)ci1.z * CIN);
            float4 u3 = *(const float4*)(cb + (size_t)ci1.w * CIN);
            float4 r, q;
            r.x = ftf32(cw0.x*v0.x + cw0.y*v1.x + cw0.z*v2.x + cw0.w*v3.x);
            r.y = ftf32(cw0.x*v0.y + cw0.y*v1.y + cw0.z*v2.y + cw0.w*v3.y);
            r.z = ftf32(cw0.x*v0.z + cw0.y*v1.z + cw0.z*v2.z + cw0.w*v3.z);
            r.w = ftf32(cw0.x*v0.w + cw0.y*v1.w + cw0.z*v2.w + cw0.w*v3.w);
            q.x = ftf32(cw1.x*u0.x + cw1.y*u1.x + cw1.z*u2.x + cw1.w*u3.x);
            q.y = ftf32(cw1.x*u0.y + cw1.y*u1.y + cw1.z*u2.y + cw1.w*u3.y);
            q.z = ftf32(cw1.x*u0.z + cw1.y*u1.z + cw1.z*u2.z + cw1.w*u3.z);
            q.w = ftf32(cw1.x*u0.w + cw1.y*u1.w + cw1.z*u2.w + cw1.w*u3.w);
            *(float4*)(Bs + SW128(r0 * 128 + c4 * 16)) = r;
            *(float4*)(Bs + SW128((r0 + 64) * 128 + c4 * 16)) = q;
        }
        asm volatile("fence.proxy.async.shared::cta;" ::: "memory");
        mbar_arrive(smb + SM_FULL(s));

        if (tid == 0) {
            mbar_wait(smb + SM_FULL(s), rnd & 1);
            uint64_t ad = mkdesc(smb + SM_A(s));
            uint64_t bd = mkdesc(smb + SM_B(s));
            #pragma unroll
            for (int k = 0; k < 4; k++)
                mma_tf32(tmem_base, ad + 2 * k, bd + 2 * k, (j > 0) || (k > 0));
            mma_commit(smb + SM_EMPTY(s));
        }
        if (++s == STAGES) { s = 0; rnd++; }
    }

    // all MMAs done when last commit lands: stage (NCHUNK-1)%3 = 2, 12th arrival -> parity 1
    mbar_wait(smb + SM_EMPTY((NCHUNK - 1) % STAGES), ((NCHUNK - 1) / STAGES) & 1);
    asm volatile("tcgen05.fence::after_thread_sync;" ::: "memory");

    // ---- epilogue: TMEM -> smem transpose -> coalesced STG ----
    float* Ts = (float*)(sm + SM_TS);
    for (int cg = 0; cg < 4; cg++) {
        if (wid < 4) {
            uint32_t r[32];
            ldtm32(r, tmem_base + cg * 32);
            asm volatile("tcgen05.wait::ld.sync.aligned;" ::: "memory");
            int oc = wid * 32 + lane;
            #pragma unroll
            for (int c = 0; c < 32; c++) Ts[oc * 33 + c] = __uint_as_float(r[c]);
        }
        __syncthreads();
        {
            int ocr = tid >> 2, q8 = (tid & 3) * 8;
            const float* row = Ts + ocr * 33 + q8;
            float* op = out + ((size_t)(b * OC + ocr)) * HW + pixbase + cg * 32 + q8;
            float v0 = row[0], v1 = row[1], v2 = row[2], v3 = row[3];
            float v4 = row[4], v5 = row[5], v6 = row[6], v7 = row[7];
            *(float4*)(op)     = make_float4(v0, v1, v2, v3);
            *(float4*)(op + 4) = make_float4(v4, v5, v6, v7);
        }
        __syncthreads();
    }

    if (wid == 0) {
        asm volatile("tcgen05.relinquish_alloc_permit.cta_group::1.sync.aligned;");
        asm volatile("tcgen05.dealloc.cta_group::1.sync.aligned.b32 %0, %1;"
                     :: "r"(tmem_base), "r"((uint32_t)TMEM_COLS));
    }
#else
    (void)out;   // non-103a PTX pass: dead body; sm_103a cubin selected at runtime
#endif
}

// ---------------- launch ----------------
extern "C" void kernel_launch(void* const* d_in, const int* in_sizes, int n_in,
                              void* d_out, int out_size) {
    const float* x   = (const float*)d_in[0];
    const float* off = (const float*)d_in[1];
    const float* w   = (const float*)d_in[2];
    float* out = (float*)d_out;
    (void)in_sizes; (void)n_in; (void)out_size;

    cudaFuncSetAttribute(main_kernel, cudaFuncAttributeMaxDynamicSharedMemorySize, SM_TOTAL);

    pad_kernel   <<<NB * HPAD, 256>>>(x);
    wkcoef_kernel<<<(NS * OC * CIN) / 256, 256>>>(w, off);
    main_kernel  <<<128, 512, SM_TOTAL>>>(out);
}

// round 5
// speedup vs baseline: 3.8339x; 1.3020x over previous
#include <cuda_runtime.h>
#include <cstdint>

#define HPAD   66
#define CIN    128
#define OC     128
#define HW     4096
#define NB     4
#define NS     9
#define NCHUNK 36
#define STAGES 3

// ---- device scratch ----
__device__ float  g_xpad[NB * HPAD * HPAD * CIN];   // NHWC padded x
__device__ float  g_wk2[NS * OC * CIN];             // [n][oc][c], tf32-rounded
__device__ float4 g_gw[NB * NS * HW];               // bilinear weights
__device__ int4   g_gi[NB * NS * HW];               // gather indices (66x66 plane)

// ---- dynamic smem layout (bytes) ----
#define SM_TPTR   0
#define SM_FULL(s)  (16 + 8 * (s))
#define SM_EMPTY(s) (48 + 8 * (s))
#define SM_A(s)   (1024 + (s) * 32768)
#define SM_B(s)   (SM_A(s) + 16384)
#define SM_TS     99328
#define SM_TOTAL  (99328 + 128 * 33 * 4)

#define TMEM_COLS 128
// idesc kind::tf32: dtype=F32(1)<<4, atype=TF32(2)<<7, btype=TF32(2)<<10,
// N>>3 (16)<<17, M>>4 (8)<<24
#define IDESC 0x8200910u

#define SW128(o) ((o) ^ (((o) >> 3) & 0x70))

// Feature gate: tcgen05 only exists in the compute_103a device pass.
#if !defined(__CUDA_ARCH__) || defined(__CUDA_ARCH_FEAT_SM103_ALL)
#define HAS_TCGEN05 1
#else
#define HAS_TCGEN05 0
#endif

// ---------------- PTX helpers ----------------
__device__ __forceinline__ uint32_t smem_u32(const void* p) {
    uint32_t a;
    asm("{ .reg .u64 t; cvta.to.shared.u64 t, %1; cvt.u32.u64 %0, t; }" : "=r"(a) : "l"(p));
    return a;
}
__device__ __forceinline__ float ftf32(float x) {
    uint32_t r; asm("cvt.rna.tf32.f32 %0, %1;" : "=r"(r) : "f"(x));
    return __uint_as_float(r);
}
__device__ __forceinline__ uint64_t mkdesc(uint32_t addr) {
    const uint64_t base = (2ull << 61) | (1ull << 46) | (64ull << 32) | (1ull << 16);
    return base | ((uint64_t)(addr >> 4) & 0x3FFF);
}
__device__ __forceinline__ void mbar_init(uint32_t a, uint32_t cnt) {
    asm volatile("mbarrier.init.shared.b64 [%0], %1;" :: "r"(a), "r"(cnt) : "memory");
}
__device__ __forceinline__ void mbar_arrive(uint32_t a) {
    asm volatile("mbarrier.arrive.shared.b64 _, [%0];" :: "r"(a) : "memory");
}
__device__ __forceinline__ void mbar_wait(uint32_t a, uint32_t par) {
    uint32_t done;
    asm volatile(
        "{\n\t.reg .pred p;\n\t"
        "mbarrier.try_wait.parity.acquire.cta.shared::cta.b64 p, [%1], %2;\n\t"
        "selp.b32 %0, 1, 0, p;\n\t}"
        : "=r"(done) : "r"(a), "r"(par) : "memory");
    if (!done) {
        asm volatile(
            "{\n\t.reg .pred P1;\n\t"
            "W%=:\n\t"
            "mbarrier.try_wait.parity.acquire.cta.shared::cta.b64 P1, [%0], %1, 0x989680;\n\t"
            "@P1 bra.uni D%=;\n\t"
            "bra.uni W%=;\n\t"
            "D%=:\n\t}"
            :: "r"(a), "r"(par) : "memory");
    }
}

#if HAS_TCGEN05
__device__ __forceinline__ void mma_tf32(uint32_t d, uint64_t ad, uint64_t bd, bool acc) {
    uint32_t e = acc ? 1u : 0u, z = 0u;
    asm volatile(
        "{\n\t.reg .pred p;\n\tsetp.ne.u32 p, %5, 0;\n\t"
        "tcgen05.mma.cta_group::1.kind::tf32 [%0], %1, %2, %3, {%4,%4,%4,%4}, p;\n\t}"
        :: "r"(d), "l"(ad), "l"(bd), "r"(IDESC), "r"(z), "r"(e) : "memory");
}
__device__ __forceinline__ void mma_commit(uint32_t mbar) {
    asm volatile(
        "tcgen05.commit.cta_group::1.mbarrier::arrive::one.shared::cluster.b64 [%0];"
        :: "r"(mbar) : "memory");
}
__device__ __forceinline__ void ldtm32(uint32_t* r, uint32_t ta) {
    asm volatile(
        "tcgen05.ld.sync.aligned.32x32b.x32.b32 "
        "{%0,%1,%2,%3,%4,%5,%6,%7,%8,%9,%10,%11,%12,%13,%14,%15,"
        "%16,%17,%18,%19,%20,%21,%22,%23,%24,%25,%26,%27,%28,%29,%30,%31}, [%32];"
        : "=r"(r[0]),"=r"(r[1]),"=r"(r[2]),"=r"(r[3]),"=r"(r[4]),"=r"(r[5]),"=r"(r[6]),"=r"(r[7]),
          "=r"(r[8]),"=r"(r[9]),"=r"(r[10]),"=r"(r[11]),"=r"(r[12]),"=r"(r[13]),"=r"(r[14]),"=r"(r[15]),
          "=r"(r[16]),"=r"(r[17]),"=r"(r[18]),"=r"(r[19]),"=r"(r[20]),"=r"(r[21]),"=r"(r[22]),"=r"(r[23]),
          "=r"(r[24]),"=r"(r[25]),"=r"(r[26]),"=r"(r[27]),"=r"(r[28]),"=r"(r[29]),"=r"(r[30]),"=r"(r[31])
        : "r"(ta));
}
#endif

// ---------------- prep kernels ----------------
// pad + NCHW->NHWC transpose, smem-staged for coalescing on both sides.
__global__ __launch_bounds__(512) void pad_kernel(const float* __restrict__ x) {
    __shared__ float ts[128 * 65];
    int bk  = blockIdx.x;
    int hp  = bk % HPAD;
    int b   = bk / HPAD;
    int tid = threadIdx.x;
    bool irow = (hp >= 1 && hp <= 64);
    if (irow) {
        const float* xr = x + ((size_t)b * CIN) * 4096 + (size_t)(hp - 1) * 64;
        #pragma unroll
        for (int i = 0; i < 16; i++) {
            int idx = tid + i * 512;
            int c = idx >> 6, wp = idx & 63;
            ts[c * 65 + wp] = xr[(size_t)c * 4096 + wp];
        }
    }
    __syncthreads();
    float* orow = g_xpad + ((size_t)(b * HPAD + hp)) * HPAD * CIN;
    #pragma unroll
    for (int i = 0; i < 5; i++) {
        int idx = tid + i * 512;              // over 66*128/4 = 2112 float4
        if (idx >= 2112) break;
        int wp = idx >> 5, c4i = idx & 31;
        float4 v = make_float4(0.f, 0.f, 0.f, 0.f);
        if (irow && wp >= 1 && wp <= 64) {
            int c = c4i * 4, w = wp - 1;
            v = make_float4(ts[c * 65 + w], ts[(c + 1) * 65 + w],
                            ts[(c + 2) * 65 + w], ts[(c + 3) * 65 + w]);
        }
        *(float4*)(orow + (size_t)idx * 4) = v;
    }
}

// fused: weight transpose+tf32 round AND bilinear coef precompute (both 147456 items)
__global__ void wkcoef_kernel(const float* __restrict__ w, const float* __restrict__ off) {
    int t = blockIdx.x * 256 + threadIdx.x;
    {   // weight: [n][oc][c] <- w[oc][c][n]
        int c  = t & 127;
        int oc = (t >> 7) & 127;
        int n  = t >> 14;
        g_wk2[(n * OC + oc) * CIN + c] = ftf32(w[(oc * CIN + c) * 9 + n]);
    }
    {   // coefs
        int pix = t & 4095;
        int n   = (t >> 12) % 9;
        int b   = t / (9 * 4096);
        int i   = pix >> 6, j = pix & 63;
        float ox = off[(b * 18 + 2 * n)     * HW + pix];
        float oy = off[(b * 18 + 2 * n + 1) * HW + pix];
        float px = (float)(i + n / 3) + ox;
        float py = (float)(j + n % 3) + oy;
        float fx = floorf(px), fy = floorf(py);
        int qltx = min(max((int)fx, 0), 65);
        int qlty = min(max((int)fy, 0), 65);
        int qrbx = min(max((int)fx + 1, 0), 65);
        int qrby = min(max((int)fy + 1, 0), 65);
        if (px < 1.f || px > 64.f) px = fx;
        if (py < 1.f || py > 64.f) py = fy;
        px = fminf(fmaxf(px, 0.f), 65.f);
        py = fminf(fmaxf(py, 0.f), 65.f);
        float dltx = 1.f + (float)qltx - px;
        float dlty = 1.f + (float)qlty - py;
        float drbx = 1.f - ((float)qrbx - px);
        float drby = 1.f - ((float)qrby - py);
        g_gw[t] = make_float4(dltx * dlty, drbx * drby, dltx * drby, drbx * dlty);
        g_gi[t] = make_int4(qltx * HPAD + qlty, qrbx * HPAD + qrby,
                            qltx * HPAD + qrby, qrbx * HPAD + qlty);
    }
}

// ------- main fused gather + tcgen05 TF32 GEMM (3-stage ring, dedicated MMA warp) -------
__global__ __launch_bounds__(544, 1) void main_kernel(float* __restrict__ out) {
#if HAS_TCGEN05
    extern __shared__ char sm[];
    uint32_t smb = smem_u32(sm);
    int tid  = threadIdx.x;
    int wid  = tid >> 5;
    int lane = tid & 31;
    int b       = blockIdx.x >> 5;
    int pixbase = (blockIdx.x & 31) << 7;

    if (wid == 0)
        asm volatile("tcgen05.alloc.cta_group::1.sync.aligned.shared::cta.b32 [%0], %1;"
                     :: "r"(smb + SM_TPTR), "r"((uint32_t)TMEM_COLS) : "memory");
    if (tid == 0) {
        #pragma unroll
        for (int s = 0; s < STAGES; s++) {
            mbar_init(smb + SM_FULL(s), 16);    // one elected arrival per builder warp
            mbar_init(smb + SM_EMPTY(s), 1);    // armed by tcgen05.commit
        }
    }
    __syncthreads();

    uint32_t tmem_base;
    asm volatile("ld.shared.b32 %0, [%1];" : "=r"(tmem_base) : "r"(smb + SM_TPTR));

    if (wid == 16) {
        // ---------------- dedicated MMA issuer warp ----------------
        if (lane == 0) {
            int s = 0, rnd = 0;
            for (int j = 0; j < NCHUNK; j++) {
                mbar_wait(smb + SM_FULL(s), rnd & 1);
                uint64_t ad = mkdesc(smb + SM_A(s));
                uint64_t bd = mkdesc(smb + SM_B(s));
                #pragma unroll
                for (int k = 0; k < 4; k++)
                    mma_tf32(tmem_base, ad + 2 * k, bd + 2 * k, (j > 0) || (k > 0));
                mma_commit(smb + SM_EMPTY(s));
                if (++s == STAGES) { s = 0; rnd++; }
            }
        }
    } else {
        // ---------------- 16 builder warps ----------------
        const float* xb = g_xpad + (size_t)b * HPAD * HPAD * CIN;
        int c4 = tid & 7, r0 = tid >> 3;             // c4: 16B group, r0: 0..63

        float4 cw0, cw1; int4 ci0, ci1;              // coef cache (2 pixels)
        int s = 0, rnd = 0;

        for (int j = 0; j < NCHUNK; j++) {
            int n = j >> 2, cc = j & 3;
            if (cc == 0) {
                const float4* gwp = g_gw + ((size_t)b * NS + n) * HW + pixbase;
                const int4*   gip = g_gi + ((size_t)b * NS + n) * HW + pixbase;
                cw0 = gwp[r0];      ci0 = gip[r0];
                cw1 = gwp[r0 + 64]; ci1 = gip[r0 + 64];
            }
            if (j >= STAGES) mbar_wait(smb + SM_EMPTY(s), (rnd - 1) & 1);

            char* As = sm + SM_A(s);
            char* Bs = sm + SM_B(s);
            // ---- A tile: wk2[n][oc][cc*32 + c4*4 ..+4], rows oc = r0, r0+64 ----
            {
                const float* wkb = g_wk2 + ((size_t)n * OC) * CIN + cc * 32 + c4 * 4;
                float4 a0 = *(const float4*)(wkb + (size_t)r0 * CIN);
                float4 a1 = *(const float4*)(wkb + (size_t)(r0 + 64) * CIN);
                *(float4*)(As + SW128(r0 * 128 + c4 * 16)) = a0;
                *(float4*)(As + SW128((r0 + 64) * 128 + c4 * 16)) = a1;
            }
            // ---- B tile: bilinear gather for pixels r0 and r0+64 ----
            {
                const float* cb = xb + cc * 32 + c4 * 4;
                float4 v0 = *(const float4*)(cb + (size_t)ci0.x * CIN);
                float4 v1 = *(const float4*)(cb + (size_t)ci0.y * CIN);
                float4 v2 = *(const float4*)(cb + (size_t)ci0.z * CIN);
                float4 v3 = *(const float4*)(cb + (size_t)ci0.w * CIN);
                float4 u0 = *(const float4*)(cb + (size_t)ci1.x * CIN);
                float4 u1 = *(const float4*)(cb + (size_t)ci1.y * CIN);
                float4 u2 = *(const float4*)(cb + (size_t)ci1.z * CIN);
                float4 u3 = *(const float4*)(cb + (size_t)ci1.w * CIN);
                float4 r, q;
                r.x = ftf32(cw0.x*v0.x + cw0.y*v1.x + cw0.z*v2.x + cw0.w*v3.x);
                r.y = ftf32(cw0.x*v0.y + cw0.y*v1.y + cw0.z*v2.y + cw0.w*v3.y);
                r.z = ftf32(cw0.x*v0.z + cw0.y*v1.z + cw0.z*v2.z + cw0.w*v3.z);
                r.w = ftf32(cw0.x*v0.w + cw0.y*v1.w + cw0.z*v2.w + cw0.w*v3.w);
                q.x = ftf32(cw1.x*u0.x + cw1.y*u1.x + cw1.z*u2.x + cw1.w*u3.x);
                q.y = ftf32(cw1.x*u0.y + cw1.y*u1.y + cw1.z*u2.y + cw1.w*u3.y);
                q.z = ftf32(cw1.x*u0.z + cw1.y*u1.z + cw1.z*u2.z + cw1.w*u3.z);
                q.w = ftf32(cw1.x*u0.w + cw1.y*u1.w + cw1.z*u2.w + cw1.w*u3.w);
                *(float4*)(Bs + SW128(r0 * 128 + c4 * 16)) = r;
                *(float4*)(Bs + SW128((r0 + 64) * 128 + c4 * 16)) = q;
            }
            asm volatile("fence.proxy.async.shared::cta;" ::: "memory");
            __syncwarp();
            if (lane == 0) mbar_arrive(smb + SM_FULL(s));
            if (++s == STAGES) { s = 0; rnd++; }
        }
    }

    // all MMAs done when last commit lands
    mbar_wait(smb + SM_EMPTY((NCHUNK - 1) % STAGES), ((NCHUNK - 1) / STAGES) & 1);
    asm volatile("tcgen05.fence::after_thread_sync;" ::: "memory");

    // ---- epilogue: TMEM -> smem transpose -> coalesced STG ----
    float* Ts = (float*)(sm + SM_TS);
    for (int cg = 0; cg < 4; cg++) {
        if (wid < 4) {
            uint32_t r[32];
            ldtm32(r, tmem_base + cg * 32);
            asm volatile("tcgen05.wait::ld.sync.aligned;" ::: "memory");
            int oc = wid * 32 + lane;
            #pragma unroll
            for (int c = 0; c < 32; c++) Ts[oc * 33 + c] = __uint_as_float(r[c]);
        }
        __syncthreads();
        if (tid < 512) {
            int ocr = tid >> 2, q8 = (tid & 3) * 8;
            const float* row = Ts + ocr * 33 + q8;
            float* op = out + ((size_t)(b * OC + ocr)) * HW + pixbase + cg * 32 + q8;
            float v0 = row[0], v1 = row[1], v2 = row[2], v3 = row[3];
            float v4 = row[4], v5 = row[5], v6 = row[6], v7 = row[7];
            *(float4*)(op)     = make_float4(v0, v1, v2, v3);
            *(float4*)(op + 4) = make_float4(v4, v5, v6, v7);
        }
        __syncthreads();
    }

    if (wid == 0) {
        asm volatile("tcgen05.relinquish_alloc_permit.cta_group::1.sync.aligned;");
        asm volatile("tcgen05.dealloc.cta_group::1.sync.aligned.b32 %0, %1;"
                     :: "r"(tmem_base), "r"((uint32_t)TMEM_COLS));
    }
#else
    (void)out;   // non-103a PTX pass: dead body; sm_103a cubin selected at runtime
#endif
}

// ---------------- launch ----------------
extern "C" void kernel_launch(void* const* d_in, const int* in_sizes, int n_in,
                              void* d_out, int out_size) {
    const float* x   = (const float*)d_in[0];
    const float* off = (const float*)d_in[1];
    const float* w   = (const float*)d_in[2];
    float* out = (float*)d_out;
    (void)in_sizes; (void)n_in; (void)out_size;

    cudaFuncSetAttribute(main_kernel, cudaFuncAttributeMaxDynamicSharedMemorySize, SM_TOTAL);

    pad_kernel   <<<NB * HPAD, 512>>>(x);
    wkcoef_kernel<<<(NS * OC * CIN) / 256, 256>>>(w, off);
    main_kernel  <<<128, 544, SM_TOTAL>>>(out);
}